// round 15
// baseline (speedup 1.0000x reference)
#include <cuda_runtime.h>
#include <cuda_bf16.h>
#include <stdint.h>

#define N_NODES_MAX 50048
#define E_MAX 1000000
#define FEAT 128
#define SCAN_BLK 256
#define ROWB 272

__device__ __align__(256) float g_dinv[N_NODES_MAX];
__device__ __align__(256) float g_agg[N_NODES_MAX * FEAT];
__device__ __align__(256) float g_h0[N_NODES_MAX * FEAT];
__device__ __align__(256) int g_degi[N_NODES_MAX];       // zero at launch entry
__device__ __align__(256) int g_offs[N_NODES_MAX + 1];
__device__ __align__(256) int g_cursor[N_NODES_MAX];
__device__ __align__(256) int g_csr[E_MAX];
__device__ __align__(256) int g_status[SCAN_BLK];        // lookback status; zero at entry

// bf16 weight blobs, [n][k] row-major: [Wl0, Wr0, Wl1, Wr1, Wfc][hi/lo]
__device__ __align__(256) unsigned char g_wb[5][2][32768];

// ===========================================================================
// helpers
// ===========================================================================
__device__ __forceinline__ uint32_t smem_u32(const void* p) {
    uint32_t a;
    asm("{ .reg .u64 t; cvta.to.shared.u64 t, %1; cvt.u32.u64 %0, t; }" : "=r"(a) : "l"(p));
    return a;
}
__device__ __forceinline__ uint32_t pack_bf16x2(float x, float y) {
    __nv_bfloat162 v(__float2bfloat16(x), __float2bfloat16(y));
    return *(uint32_t*)&v;
}
__device__ __forceinline__ void ldmatrix_x4(uint32_t* r, uint32_t addr) {
    asm volatile("ldmatrix.sync.aligned.m8n8.x4.shared.b16 {%0,%1,%2,%3}, [%4];"
                 : "=r"(r[0]), "=r"(r[1]), "=r"(r[2]), "=r"(r[3]) : "r"(addr));
}
__device__ __forceinline__ void mma16816(float* d, const uint32_t* a, uint32_t b0, uint32_t b1) {
    asm volatile("mma.sync.aligned.m16n8k16.row.col.f32.bf16.bf16.f32 "
                 "{%0,%1,%2,%3}, {%4,%5,%6,%7}, {%8,%9}, {%0,%1,%2,%3};"
                 : "+f"(d[0]), "+f"(d[1]), "+f"(d[2]), "+f"(d[3])
                 : "r"(a[0]), "r"(a[1]), "r"(a[2]), "r"(a[3]), "r"(b0), "r"(b1));
}

// 3-pass hi/lo HMMA: Ah*Bh + Al*Bh + Ah*Bl, accumulated into acc.
template<int NP>
__device__ __forceinline__ void mma_passes(uint32_t aAddrBase, uint32_t bAddrBase,
                                           uint32_t aLoOff, uint32_t bLoOff,
                                           float (&acc)[2][2 * NP][4]) {
#pragma unroll
    for (int pass = 0; pass < 3; pass++) {
        uint32_t aBase = aAddrBase + ((pass == 1) ? aLoOff : 0u);
        uint32_t bBase = bAddrBase + ((pass == 2) ? bLoOff : 0u);
#pragma unroll
        for (int ks = 0; ks < 8; ks++) {
            uint32_t kOff = ks * 32;
            uint32_t af[2][4];
            ldmatrix_x4(af[0], aBase + kOff);
            ldmatrix_x4(af[1], aBase + 16 * ROWB + kOff);
            uint32_t bf[NP][4];
#pragma unroll
            for (int p = 0; p < NP; p++)
                ldmatrix_x4(bf[p], bBase + (uint32_t)(p * 16) * ROWB + kOff);
#pragma unroll
            for (int t = 0; t < 2; t++)
#pragma unroll
                for (int p = 0; p < NP; p++) {
                    mma16816(acc[t][2 * p + 0], af[t], bf[p][0], bf[p][1]);
                    mma16816(acc[t][2 * p + 1], af[t], bf[p][2], bf[p][3]);
                }
        }
    }
}

__device__ __forceinline__ int edge_idx(const void* ei, long long pos, int is64) {
    if (is64) return (int)((const long long*)ei)[pos];
    return ((const int*)ei)[pos];
}

// per-block edge-dtype detection: int64 data => odd 32-bit words all zero.
__device__ __forceinline__ int detect_is64(const void* ei, int E) {
    int any = 0;
    if (threadIdx.x < 64) {
        int pos = 1 + 2 * threadIdx.x;
        if (pos < 2 * E && ((const int*)ei)[pos] != 0) any = 1;
    }
    return !__syncthreads_or(any);
}

// ===========================================================================
// degree histogram + weight prep fused
// ===========================================================================
__global__ void degree_prep(const void* __restrict__ ei, int* __restrict__ degi,
                            int E, int M, int degBlocks,
                            const float* __restrict__ W0, const float* __restrict__ W1,
                            const float* __restrict__ W2, const float* __restrict__ W3,
                            const float* __restrict__ W4, unsigned char* __restrict__ wb) {
    if (blockIdx.x < (unsigned)degBlocks) {
        int is64 = detect_is64(ei, E);
        int e = blockIdx.x * blockDim.x + threadIdx.x;
        if (e >= E) return;
        int d = edge_idx(ei, (long long)E + e, is64);
        if (d < 0 || d >= M) return;
        atomicAdd(&degi[d], 1);
    } else {
        int pb = blockIdx.x - degBlocks;       // 0..319
        int w = pb >> 6;                        // weight id 0..4
        int N = (w == 4) ? 64 : 128;
        int idx = (pb & 63) * blockDim.x + threadIdx.x;
        if (idx >= N * 128) return;
        const float* W = (w == 0) ? W0 : (w == 1) ? W1 : (w == 2) ? W2 : (w == 3) ? W3 : W4;
        unsigned char* bh = wb + ((size_t)w * 2 + 0) * 32768;
        unsigned char* bl = wb + ((size_t)w * 2 + 1) * 32768;
        int n = idx >> 7, k = idx & 127;
        float wv = W[k * N + n];
        __nv_bfloat16 h = __float2bfloat16(wv);
        __nv_bfloat16 l = __float2bfloat16(wv - __bfloat162float(h));
        *(__nv_bfloat16*)(bh + n * 256 + k * 2) = h;
        *(__nv_bfloat16*)(bl + n * 256 + k * 2) = l;
    }
}

// ===========================================================================
// fused scan (decoupled lookback): degi -> offs/cursor/dinv.
// ===========================================================================
__global__ void __launch_bounds__(SCAN_BLK)
scan_fused(const int* __restrict__ degi, int* __restrict__ offs,
           int* __restrict__ cursor, float* __restrict__ dinv,
           int* __restrict__ status, int M) {
    __shared__ int sh[SCAN_BLK];
    __shared__ int red[SCAN_BLK];
    const int b = blockIdx.x;
    const int tid = threadIdx.x;
    const int i = b * SCAN_BLK + tid;

    int v = (i < M) ? degi[i] : 0;
    sh[tid] = v;
    __syncthreads();
#pragma unroll
    for (int off = 1; off < SCAN_BLK; off <<= 1) {
        int t = (tid >= off) ? sh[tid - off] : 0;
        __syncthreads();
        sh[tid] += t;
        __syncthreads();
    }
    if (tid == 0) atomicExch(&status[b], sh[SCAN_BLK - 1] | (1 << 30));

    int mysum = 0;
    for (int j = tid; j < b; j += SCAN_BLK) {
        int s;
        do { s = *(volatile int*)&status[j]; } while (s == 0);
        mysum += s & 0x3FFFFFFF;
    }
    red[tid] = mysum;
    __syncthreads();
#pragma unroll
    for (int off = SCAN_BLK / 2; off > 0; off >>= 1) {
        if (tid < off) red[tid] += red[tid + off];
        __syncthreads();
    }
    int prefix = red[0];

    if (i >= M) return;
    int inc = sh[tid] + prefix;
    offs[i + 1] = inc;
    cursor[i] = inc - v;
    dinv[i] = 1.0f / fmaxf((float)v, 1.0f);
    if (i == 0) offs[0] = 0;
}

__global__ void csr_fill(const void* __restrict__ ei, int* __restrict__ cursor,
                         int* __restrict__ csr, int E, int M) {
    int is64 = detect_is64(ei, E);
    int e = blockIdx.x * blockDim.x + threadIdx.x;
    if (e >= E) return;
    int s = edge_idx(ei, e, is64);
    int d = edge_idx(ei, (long long)E + e, is64);
    if (s < 0 || s >= M || d < 0 || d >= M) return;
    int slot = atomicAdd(&cursor[d], 1);
    csr[slot] = s;
}

// ===========================================================================
// gather: one warp per node; unroll-4 (measured optimum). Tail resets degi
// and scan status for the next launch.
// ===========================================================================
__global__ void __launch_bounds__(256)
gather_kernel(const float* __restrict__ feat, const int* __restrict__ csr,
              const int* __restrict__ offs, const float* __restrict__ dinv,
              float* __restrict__ agg, int* __restrict__ degi,
              int* __restrict__ status, int M) {
    if (blockIdx.x == 0 && threadIdx.x < SCAN_BLK) status[threadIdx.x] = 0;
    int warp = (blockIdx.x * blockDim.x + threadIdx.x) >> 5;
    int lane = threadIdx.x & 31;
    if (warp >= M) return;
    if (lane == 0) degi[warp] = 0;
    int beg = offs[warp], end = offs[warp + 1];
    float4 acc = make_float4(0.f, 0.f, 0.f, 0.f);
    int j = beg;
    for (; j + 4 <= end; j += 4) {
        int s0 = csr[j], s1 = csr[j + 1], s2 = csr[j + 2], s3 = csr[j + 3];
        float4 v0 = *((const float4*)(feat + (size_t)s0 * FEAT) + lane);
        float4 v1 = *((const float4*)(feat + (size_t)s1 * FEAT) + lane);
        float4 v2 = *((const float4*)(feat + (size_t)s2 * FEAT) + lane);
        float4 v3 = *((const float4*)(feat + (size_t)s3 * FEAT) + lane);
        acc.x += (v0.x + v1.x) + (v2.x + v3.x);
        acc.y += (v0.y + v1.y) + (v2.y + v3.y);
        acc.z += (v0.z + v1.z) + (v2.z + v3.z);
        acc.w += (v0.w + v1.w) + (v2.w + v3.w);
    }
    for (; j < end; j++) {
        int s = csr[j];
        float4 v = *((const float4*)(feat + (size_t)s * FEAT) + lane);
        acc.x += v.x; acc.y += v.y; acc.z += v.z; acc.w += v.w;
    }
    float sc = dinv[warp];
    acc.x *= sc; acc.y *= sc; acc.z *= sc; acc.w *= sc;
    *((float4*)(agg + (size_t)warp * FEAT) + lane) = acc;
}

// ===========================================================================
// HMMA GEMM, 512 threads (16 warps, 4x4 warp grid, 32x32 per warp) to raise
// warp occupancy 25%->50% and hide ldmatrix->mma latency. Front-loaded fills
// (A0, A1, B0 before first sync), B1 swapped after op0.
// FC=true: h -> A0 slot, Bfc -> B slot, then FC MMA (warp covers 32x16).
// ===========================================================================
#define GEMM_THR 512
#define SM_A0H 0
#define SM_A0L (128 * ROWB)
#define SM_A1H (2 * 128 * ROWB)
#define SM_A1L (3 * 128 * ROWB)
#define SM_B   (4 * 128 * ROWB)
#define A_TILE_BYTES (128 * ROWB)
#define SMEM_TOTAL (6 * 128 * ROWB)   // 208896

template<bool FC>
__global__ void __launch_bounds__(GEMM_THR)
sage_gemm(const float* __restrict__ A0, const float* __restrict__ A1,
          const unsigned char* __restrict__ B0h, const unsigned char* __restrict__ B0l,
          const unsigned char* __restrict__ B1h, const unsigned char* __restrict__ B1l,
          const float* __restrict__ bias, float* __restrict__ hout,
          const unsigned char* __restrict__ Bfh, const unsigned char* __restrict__ Bfl,
          const float* __restrict__ bfc, float* __restrict__ fcout, int M) {
    extern __shared__ __align__(16) unsigned char smem[];
    constexpr uint32_t A_LO = A_TILE_BYTES;
    constexpr uint32_t B_LO_LAYER = 128 * ROWB;
    constexpr uint32_t B_LO_FC = 64 * ROWB;

    const int tid  = threadIdx.x;
    const int wid  = tid >> 5;            // 0..15
    const int lane = tid & 31;
    const int mw   = wid >> 2;            // 0..3
    const int nw   = wid & 3;             // 0..3
    const int mbase = mw * 32;
    const int m0 = blockIdx.x * 128;
    const uint32_t sb = smem_u32(smem);

    const uint32_t aRowSel = (uint32_t)(mbase + (lane & 15)) * ROWB + ((lane >> 4) & 1) * 16;
    const uint32_t aAddr0 = sb + SM_A0H + aRowSel;
    const uint32_t aAddr1 = sb + SM_A1H + aRowSel;
    const uint32_t bRowPart = (uint32_t)((lane & 7) + ((lane >> 4) & 1) * 8);
    const uint32_t bAddr32  = sb + SM_B + (nw * 32 + bRowPart) * ROWB + ((lane >> 3) & 1) * 16;
    const uint32_t bAddr16  = sb + SM_B + (nw * 16 + bRowPart) * ROWB + ((lane >> 3) & 1) * 16;

    float acc[2][4][4];                   // warp: 32 rows x 32 cols
#pragma unroll
    for (int t = 0; t < 2; t++)
#pragma unroll
        for (int j = 0; j < 4; j++)
#pragma unroll
            for (int q = 0; q < 4; q++) acc[t][j][q] = 0.0f;

    // ---- front-loaded fills: A0, A1, B0 ----
#pragma unroll
    for (int op = 0; op < 2; op++) {
        const float* A = (op == 0) ? A0 : A1;
        const uint32_t base_h = (op == 0) ? SM_A0H : SM_A1H;
        const uint32_t base_l = (op == 0) ? SM_A0L : SM_A1L;
#pragma unroll
        for (int i = 0; i < 8; i++) {
            int g = tid + GEMM_THR * i;   // 4096 float4 groups
            int r = g >> 5;
            int kb = (g & 31) << 2;
            int gr = m0 + r;
            float4 a = make_float4(0.f, 0.f, 0.f, 0.f);
            if (gr < M) a = *(const float4*)(A + (size_t)gr * FEAT + kb);
            __nv_bfloat16 hx = __float2bfloat16(a.x), hy = __float2bfloat16(a.y);
            __nv_bfloat16 hz = __float2bfloat16(a.z), hw = __float2bfloat16(a.w);
            uint2 hv, lv;
            {
                __nv_bfloat162 p0(hx, hy), p1(hz, hw);
                hv.x = *(uint32_t*)&p0; hv.y = *(uint32_t*)&p1;
            }
            lv.x = pack_bf16x2(a.x - __bfloat162float(hx), a.y - __bfloat162float(hy));
            lv.y = pack_bf16x2(a.z - __bfloat162float(hz), a.w - __bfloat162float(hw));
            uint32_t off = (uint32_t)r * ROWB + kb * 2;
            *(uint2*)(smem + base_h + off) = hv;
            *(uint2*)(smem + base_l + off) = lv;
        }
    }
#pragma unroll
    for (int i = 0; i < 4; i++) {
        int g = tid + GEMM_THR * i;       // 2048 uint4 per blob
        int row = g >> 4, col = g & 15;
        uint32_t off = (uint32_t)row * ROWB + col * 16;
        *(uint4*)(smem + SM_B + off) = ((const uint4*)B0h)[g];
        *(uint4*)(smem + SM_B + B_LO_LAYER + off) = ((const uint4*)B0l)[g];
    }
    __syncthreads();

    // ---- op0 MMA ----
    mma_passes<2>(aAddr0, bAddr32, A_LO, B_LO_LAYER, acc);
    __syncthreads();

    // ---- swap in B1 ----
#pragma unroll
    for (int i = 0; i < 4; i++) {
        int g = tid + GEMM_THR * i;
        int row = g >> 4, col = g & 15;
        uint32_t off = (uint32_t)row * ROWB + col * 16;
        *(uint4*)(smem + SM_B + off) = ((const uint4*)B1h)[g];
        *(uint4*)(smem + SM_B + B_LO_LAYER + off) = ((const uint4*)B1l)[g];
    }
    __syncthreads();

    // ---- op1 MMA ----
    mma_passes<2>(aAddr1, bAddr32, A_LO, B_LO_LAYER, acc);

    const int group = lane >> 2;
    const int tig   = lane & 3;

    if (!FC) {
#pragma unroll
        for (int t = 0; t < 2; t++) {
#pragma unroll
            for (int j = 0; j < 4; j++) {
                int col = nw * 32 + j * 8 + tig * 2;
                float2 b = *(const float2*)(bias + col);
                int r0 = m0 + mbase + t * 16 + group;
                float2 o0, o1;
                o0.x = fmaxf(acc[t][j][0] + b.x, 0.f); o0.y = fmaxf(acc[t][j][1] + b.y, 0.f);
                o1.x = fmaxf(acc[t][j][2] + b.x, 0.f); o1.y = fmaxf(acc[t][j][3] + b.y, 0.f);
                if (r0 < M)     *(float2*)(hout + (size_t)r0 * FEAT + col)       = o0;
                if (r0 + 8 < M) *(float2*)(hout + (size_t)(r0 + 8) * FEAT + col) = o1;
            }
        }
    } else {
        // ---- FC stage: h = relu(acc + b) -> A0 slot; Bfc -> B slot ----
        __syncthreads();
#pragma unroll
        for (int t = 0; t < 2; t++) {
#pragma unroll
            for (int j = 0; j < 4; j++) {
                int col = nw * 32 + j * 8 + tig * 2;
                float2 b = *(const float2*)(bias + col);
                int r0 = mbase + t * 16 + group;
                float h0v = fmaxf(acc[t][j][0] + b.x, 0.f);
                float h1v = fmaxf(acc[t][j][1] + b.y, 0.f);
                float h2v = fmaxf(acc[t][j][2] + b.x, 0.f);
                float h3v = fmaxf(acc[t][j][3] + b.y, 0.f);
                __nv_bfloat16 e0 = __float2bfloat16(h0v), e1 = __float2bfloat16(h1v);
                __nv_bfloat16 e2 = __float2bfloat16(h2v), e3 = __float2bfloat16(h3v);
                uint32_t hi0, hi1;
                {
                    __nv_bfloat162 p0(e0, e1), p1(e2, e3);
                    hi0 = *(uint32_t*)&p0; hi1 = *(uint32_t*)&p1;
                }
                uint32_t lo0 = pack_bf16x2(h0v - __bfloat162float(e0), h1v - __bfloat162float(e1));
                uint32_t lo1 = pack_bf16x2(h2v - __bfloat162float(e2), h3v - __bfloat162float(e3));
                uint32_t off0 = (uint32_t)r0 * ROWB + col * 2;
                uint32_t off1 = (uint32_t)(r0 + 8) * ROWB + col * 2;
                *(uint32_t*)(smem + SM_A0H + off0) = hi0;
                *(uint32_t*)(smem + SM_A0L + off0) = lo0;
                *(uint32_t*)(smem + SM_A0H + off1) = hi1;
                *(uint32_t*)(smem + SM_A0L + off1) = lo1;
            }
        }
#pragma unroll
        for (int i = 0; i < 2; i++) {
            int g = tid + GEMM_THR * i;   // 1024 uint4 per blob
            int row = g >> 4, col = g & 15;
            uint32_t off = (uint32_t)row * ROWB + col * 16;
            *(uint4*)(smem + SM_B + off) = ((const uint4*)Bfh)[g];
            *(uint4*)(smem + SM_B + B_LO_FC + off) = ((const uint4*)Bfl)[g];
        }
        __syncthreads();

        float accf[2][2][4];              // warp: 32 rows x 16 cols
#pragma unroll
        for (int t = 0; t < 2; t++)
#pragma unroll
            for (int j = 0; j < 2; j++)
#pragma unroll
                for (int q = 0; q < 4; q++) accf[t][j][q] = 0.0f;

        mma_passes<1>(aAddr0, bAddr16, A_LO, B_LO_FC, accf);

#pragma unroll
        for (int t = 0; t < 2; t++) {
#pragma unroll
            for (int j = 0; j < 2; j++) {
                int col = nw * 16 + j * 8 + tig * 2;
                float2 b = *(const float2*)(bfc + col);
                int r0 = m0 + mbase + t * 16 + group;
                float2 o0, o1;
                o0.x = accf[t][j][0] + b.x; o0.y = accf[t][j][1] + b.y;
                o1.x = accf[t][j][2] + b.x; o1.y = accf[t][j][3] + b.y;
                if (r0 < M)     *(float2*)(fcout + (size_t)r0 * 64 + col)       = o0;
                if (r0 + 8 < M) *(float2*)(fcout + (size_t)(r0 + 8) * 64 + col) = o1;
            }
        }
    }
}

// ===========================================================================
extern "C" void kernel_launch(void* const* d_in, const int* in_sizes, int n_in,
                              void* d_out, int out_size) {
    const float* x   = (const float*)d_in[0];
    const void*  ei  = d_in[1];
    const float* Wl0 = (const float*)d_in[2];
    const float* Wr0 = (const float*)d_in[3];
    const float* b0  = (const float*)d_in[4];
    const float* Wl1 = (const float*)d_in[5];
    const float* Wr1 = (const float*)d_in[6];
    const float* b1  = (const float*)d_in[7];
    const float* Wfc = (const float*)d_in[8];
    const float* bfc = (const float*)d_in[9];
    float*       out = (float*)d_out;

    const int M = in_sizes[0] / FEAT;   // 50000
    const int E = in_sizes[1] / 2;      // 800000

    float *dinv, *agg, *h0;
    int *degi, *offs, *cursor, *csr, *status;
    unsigned char* wb;
    cudaGetSymbolAddress((void**)&dinv, g_dinv);
    cudaGetSymbolAddress((void**)&agg,  g_agg);
    cudaGetSymbolAddress((void**)&h0,   g_h0);
    cudaGetSymbolAddress((void**)&degi, g_degi);
    cudaGetSymbolAddress((void**)&offs, g_offs);
    cudaGetSymbolAddress((void**)&cursor, g_cursor);
    cudaGetSymbolAddress((void**)&csr,  g_csr);
    cudaGetSymbolAddress((void**)&status, g_status);
    cudaGetSymbolAddress((void**)&wb,   g_wb);
    auto blob = [&](int w, int hl) { return wb + ((size_t)w * 2 + hl) * 32768; };

    cudaFuncSetAttribute(sage_gemm<false>, cudaFuncAttributeMaxDynamicSharedMemorySize, SMEM_TOTAL);
    cudaFuncSetAttribute(sage_gemm<true>,  cudaFuncAttributeMaxDynamicSharedMemorySize, SMEM_TOTAL);

    // K1: degree histogram + weight prep (per-block dtype detect; degi enters 0)
    const int degBlocks = (E + 255) / 256;
    degree_prep<<<degBlocks + 320, 256>>>(ei, degi, E, M, degBlocks,
                                          Wl0, Wr0, Wl1, Wr1, Wfc, wb);

    // K2: fused decoupled-lookback scan -> offs/cursor/dinv
    const int nb = (M + SCAN_BLK - 1) / SCAN_BLK;
    scan_fused<<<nb, SCAN_BLK>>>(degi, offs, cursor, dinv, status, M);

    // K3: CSR fill
    csr_fill<<<(E + 255) / 256, 256>>>(ei, cursor, csr, E, M);

    const int gatherBlocks = (M * 32 + 255) / 256;
    const int gemmBlocks   = (M + 127) / 128;

    // layer 0: h0 = relu(agg(x)@Wl0 + x@Wr0 + b0)
    gather_kernel<<<gatherBlocks, 256>>>(x, csr, offs, dinv, agg, degi, status, M);
    sage_gemm<false><<<gemmBlocks, GEMM_THR, SMEM_TOTAL>>>(
        agg, x, blob(0, 0), blob(0, 1), blob(1, 0), blob(1, 1), b0, h0,
        nullptr, nullptr, nullptr, nullptr, M);

    // layer 1 + fc: out = relu(agg(h0)@Wl1 + h0@Wr1 + b1) @ Wfc + bfc
    gather_kernel<<<gatherBlocks, 256>>>(h0, csr, offs, dinv, agg, degi, status, M);
    sage_gemm<true><<<gemmBlocks, GEMM_THR, SMEM_TOTAL>>>(
        agg, h0, blob(2, 0), blob(2, 1), blob(3, 0), blob(3, 1), b1, nullptr,
        blob(4, 0), blob(4, 1), bfc, out, M);
}

// round 16
// speedup vs baseline: 1.7362x; 1.7362x over previous
#include <cuda_runtime.h>
#include <cuda_bf16.h>
#include <stdint.h>

#define N_NODES_MAX 50048
#define E_MAX 1000000
#define FEAT 128
#define SCAN_BLK 256
#define ROWB 272

__device__ __align__(256) float g_dinv[N_NODES_MAX];
__device__ __align__(256) float g_agg[N_NODES_MAX * FEAT];
__device__ __align__(256) float g_h0[N_NODES_MAX * FEAT];
__device__ __align__(256) int g_degi[N_NODES_MAX];       // zero at launch entry
__device__ __align__(256) int g_offs[N_NODES_MAX + 1];
__device__ __align__(256) int g_cursor[N_NODES_MAX];
__device__ __align__(256) int g_csr[E_MAX];
__device__ __align__(256) int g_status[SCAN_BLK];        // lookback status; zero at entry

// bf16 weight blobs, [n][k] row-major: [Wl0, Wr0, Wl1, Wr1, Wfc][hi/lo]
__device__ __align__(256) unsigned char g_wb[5][2][32768];

// ===========================================================================
// helpers
// ===========================================================================
__device__ __forceinline__ uint32_t smem_u32(const void* p) {
    uint32_t a;
    asm("{ .reg .u64 t; cvta.to.shared.u64 t, %1; cvt.u32.u64 %0, t; }" : "=r"(a) : "l"(p));
    return a;
}
__device__ __forceinline__ uint32_t pack_bf16x2(float x, float y) {
    __nv_bfloat162 v(__float2bfloat16(x), __float2bfloat16(y));
    return *(uint32_t*)&v;
}
__device__ __forceinline__ void ldmatrix_x4(uint32_t* r, uint32_t addr) {
    asm volatile("ldmatrix.sync.aligned.m8n8.x4.shared.b16 {%0,%1,%2,%3}, [%4];"
                 : "=r"(r[0]), "=r"(r[1]), "=r"(r[2]), "=r"(r[3]) : "r"(addr));
}
__device__ __forceinline__ void mma16816(float* d, const uint32_t* a, uint32_t b0, uint32_t b1) {
    asm volatile("mma.sync.aligned.m16n8k16.row.col.f32.bf16.bf16.f32 "
                 "{%0,%1,%2,%3}, {%4,%5,%6,%7}, {%8,%9}, {%0,%1,%2,%3};"
                 : "+f"(d[0]), "+f"(d[1]), "+f"(d[2]), "+f"(d[3])
                 : "r"(a[0]), "r"(a[1]), "r"(a[2]), "r"(a[3]), "r"(b0), "r"(b1));
}

// Fused hi/lo HMMA: per k-step load Ah/Al/Bh/Bl fragments ONCE (12 ldmatrix)
// and issue all 3 groups (Ah*Bh + Al*Bh + Ah*Bl = 6*NP MMAs). 33% fewer
// shared loads than the 3-pass version; loads front-run the dependent MMAs.
template<int NP>
__device__ __forceinline__ void mma_fused(uint32_t aHi, uint32_t bHi,
                                          uint32_t aLoOff, uint32_t bLoOff,
                                          float (&acc)[2][2 * NP][4]) {
#pragma unroll
    for (int ks = 0; ks < 8; ks++) {
        uint32_t kOff = ks * 32;
        uint32_t ah[2][4], al[2][4];
        ldmatrix_x4(ah[0], aHi + kOff);
        ldmatrix_x4(ah[1], aHi + 16 * ROWB + kOff);
        ldmatrix_x4(al[0], aHi + aLoOff + kOff);
        ldmatrix_x4(al[1], aHi + aLoOff + 16 * ROWB + kOff);
        uint32_t bh[NP][4], bl[NP][4];
#pragma unroll
        for (int p = 0; p < NP; p++) {
            ldmatrix_x4(bh[p], bHi + (uint32_t)(p * 16) * ROWB + kOff);
            ldmatrix_x4(bl[p], bHi + bLoOff + (uint32_t)(p * 16) * ROWB + kOff);
        }
#pragma unroll
        for (int t = 0; t < 2; t++)
#pragma unroll
            for (int p = 0; p < NP; p++) {
                mma16816(acc[t][2 * p + 0], ah[t], bh[p][0], bh[p][1]);
                mma16816(acc[t][2 * p + 1], ah[t], bh[p][2], bh[p][3]);
                mma16816(acc[t][2 * p + 0], al[t], bh[p][0], bh[p][1]);
                mma16816(acc[t][2 * p + 1], al[t], bh[p][2], bh[p][3]);
                mma16816(acc[t][2 * p + 0], ah[t], bl[p][0], bl[p][1]);
                mma16816(acc[t][2 * p + 1], ah[t], bl[p][2], bl[p][3]);
            }
    }
}

__device__ __forceinline__ int edge_idx(const void* ei, long long pos, int is64) {
    if (is64) return (int)((const long long*)ei)[pos];
    return ((const int*)ei)[pos];
}

// per-block edge-dtype detection: int64 data => odd 32-bit words all zero.
__device__ __forceinline__ int detect_is64(const void* ei, int E) {
    int any = 0;
    if (threadIdx.x < 64) {
        int pos = 1 + 2 * threadIdx.x;
        if (pos < 2 * E && ((const int*)ei)[pos] != 0) any = 1;
    }
    return !__syncthreads_or(any);
}

// ===========================================================================
// degree histogram + weight prep fused
// ===========================================================================
__global__ void degree_prep(const void* __restrict__ ei, int* __restrict__ degi,
                            int E, int M, int degBlocks,
                            const float* __restrict__ W0, const float* __restrict__ W1,
                            const float* __restrict__ W2, const float* __restrict__ W3,
                            const float* __restrict__ W4, unsigned char* __restrict__ wb) {
    if (blockIdx.x < (unsigned)degBlocks) {
        int is64 = detect_is64(ei, E);
        int e = blockIdx.x * blockDim.x + threadIdx.x;
        if (e >= E) return;
        int d = edge_idx(ei, (long long)E + e, is64);
        if (d < 0 || d >= M) return;
        atomicAdd(&degi[d], 1);
    } else {
        int pb = blockIdx.x - degBlocks;       // 0..319
        int w = pb >> 6;                        // weight id 0..4
        int N = (w == 4) ? 64 : 128;
        int idx = (pb & 63) * blockDim.x + threadIdx.x;
        if (idx >= N * 128) return;
        const float* W = (w == 0) ? W0 : (w == 1) ? W1 : (w == 2) ? W2 : (w == 3) ? W3 : W4;
        unsigned char* bh = wb + ((size_t)w * 2 + 0) * 32768;
        unsigned char* bl = wb + ((size_t)w * 2 + 1) * 32768;
        int n = idx >> 7, k = idx & 127;
        float wv = W[k * N + n];
        __nv_bfloat16 h = __float2bfloat16(wv);
        __nv_bfloat16 l = __float2bfloat16(wv - __bfloat162float(h));
        *(__nv_bfloat16*)(bh + n * 256 + k * 2) = h;
        *(__nv_bfloat16*)(bl + n * 256 + k * 2) = l;
    }
}

// ===========================================================================
// fused scan (decoupled lookback): degi -> offs/cursor/dinv.
// ===========================================================================
__global__ void __launch_bounds__(SCAN_BLK)
scan_fused(const int* __restrict__ degi, int* __restrict__ offs,
           int* __restrict__ cursor, float* __restrict__ dinv,
           int* __restrict__ status, int M) {
    __shared__ int sh[SCAN_BLK];
    __shared__ int red[SCAN_BLK];
    const int b = blockIdx.x;
    const int tid = threadIdx.x;
    const int i = b * SCAN_BLK + tid;

    int v = (i < M) ? degi[i] : 0;
    sh[tid] = v;
    __syncthreads();
#pragma unroll
    for (int off = 1; off < SCAN_BLK; off <<= 1) {
        int t = (tid >= off) ? sh[tid - off] : 0;
        __syncthreads();
        sh[tid] += t;
        __syncthreads();
    }
    if (tid == 0) atomicExch(&status[b], sh[SCAN_BLK - 1] | (1 << 30));

    int mysum = 0;
    for (int j = tid; j < b; j += SCAN_BLK) {
        int s;
        do { s = *(volatile int*)&status[j]; } while (s == 0);
        mysum += s & 0x3FFFFFFF;
    }
    red[tid] = mysum;
    __syncthreads();
#pragma unroll
    for (int off = SCAN_BLK / 2; off > 0; off >>= 1) {
        if (tid < off) red[tid] += red[tid + off];
        __syncthreads();
    }
    int prefix = red[0];

    if (i >= M) return;
    int inc = sh[tid] + prefix;
    offs[i + 1] = inc;
    cursor[i] = inc - v;
    dinv[i] = 1.0f / fmaxf((float)v, 1.0f);
    if (i == 0) offs[0] = 0;
}

__global__ void csr_fill(const void* __restrict__ ei, int* __restrict__ cursor,
                         int* __restrict__ csr, int E, int M) {
    int is64 = detect_is64(ei, E);
    int e = blockIdx.x * blockDim.x + threadIdx.x;
    if (e >= E) return;
    int s = edge_idx(ei, e, is64);
    int d = edge_idx(ei, (long long)E + e, is64);
    if (s < 0 || s >= M || d < 0 || d >= M) return;
    int slot = atomicAdd(&cursor[d], 1);
    csr[slot] = s;
}

// ===========================================================================
// gather: one warp per node; unroll-4 (measured optimum). Tail resets degi
// and scan status for the next launch.
// ===========================================================================
__global__ void __launch_bounds__(256)
gather_kernel(const float* __restrict__ feat, const int* __restrict__ csr,
              const int* __restrict__ offs, const float* __restrict__ dinv,
              float* __restrict__ agg, int* __restrict__ degi,
              int* __restrict__ status, int M) {
    if (blockIdx.x == 0 && threadIdx.x < SCAN_BLK) status[threadIdx.x] = 0;
    int warp = (blockIdx.x * blockDim.x + threadIdx.x) >> 5;
    int lane = threadIdx.x & 31;
    if (warp >= M) return;
    if (lane == 0) degi[warp] = 0;
    int beg = offs[warp], end = offs[warp + 1];
    float4 acc = make_float4(0.f, 0.f, 0.f, 0.f);
    int j = beg;
    for (; j + 4 <= end; j += 4) {
        int s0 = csr[j], s1 = csr[j + 1], s2 = csr[j + 2], s3 = csr[j + 3];
        float4 v0 = *((const float4*)(feat + (size_t)s0 * FEAT) + lane);
        float4 v1 = *((const float4*)(feat + (size_t)s1 * FEAT) + lane);
        float4 v2 = *((const float4*)(feat + (size_t)s2 * FEAT) + lane);
        float4 v3 = *((const float4*)(feat + (size_t)s3 * FEAT) + lane);
        acc.x += (v0.x + v1.x) + (v2.x + v3.x);
        acc.y += (v0.y + v1.y) + (v2.y + v3.y);
        acc.z += (v0.z + v1.z) + (v2.z + v3.z);
        acc.w += (v0.w + v1.w) + (v2.w + v3.w);
    }
    for (; j < end; j++) {
        int s = csr[j];
        float4 v = *((const float4*)(feat + (size_t)s * FEAT) + lane);
        acc.x += v.x; acc.y += v.y; acc.z += v.z; acc.w += v.w;
    }
    float sc = dinv[warp];
    acc.x *= sc; acc.y *= sc; acc.z *= sc; acc.w *= sc;
    *((float4*)(agg + (size_t)warp * FEAT) + lane) = acc;
}

// ===========================================================================
// HMMA GEMM (R14 structure: 256 thr, 4x2 warps, front-loaded fills) with
// fused hi/lo k-loop (register-reused fragments, 12 ldmatrix : 24 MMA).
// FC=true: h -> A0 slot, Bfc -> B slot, then FC MMA.
// ===========================================================================
#define SM_A0H 0
#define SM_A0L (128 * ROWB)
#define SM_A1H (2 * 128 * ROWB)
#define SM_A1L (3 * 128 * ROWB)
#define SM_B   (4 * 128 * ROWB)
#define A_TILE_BYTES (128 * ROWB)
#define SMEM_TOTAL (6 * 128 * ROWB)   // 208896

template<bool FC>
__global__ void __launch_bounds__(256)
sage_gemm(const float* __restrict__ A0, const float* __restrict__ A1,
          const unsigned char* __restrict__ B0h, const unsigned char* __restrict__ B0l,
          const unsigned char* __restrict__ B1h, const unsigned char* __restrict__ B1l,
          const float* __restrict__ bias, float* __restrict__ hout,
          const unsigned char* __restrict__ Bfh, const unsigned char* __restrict__ Bfl,
          const float* __restrict__ bfc, float* __restrict__ fcout, int M) {
    extern __shared__ __align__(16) unsigned char smem[];
    constexpr uint32_t A_LO = A_TILE_BYTES;
    constexpr uint32_t B_LO_LAYER = 128 * ROWB;
    constexpr uint32_t B_LO_FC = 64 * ROWB;

    const int tid  = threadIdx.x;
    const int wid  = tid >> 5;
    const int lane = tid & 31;
    const int mw   = wid >> 1;
    const int nw   = wid & 1;
    const int mbase = mw * 32;
    const int m0 = blockIdx.x * 128;
    const uint32_t sb = smem_u32(smem);

    const uint32_t aRowSel = (uint32_t)(mbase + (lane & 15)) * ROWB + ((lane >> 4) & 1) * 16;
    const uint32_t aAddr0 = sb + SM_A0H + aRowSel;
    const uint32_t aAddr1 = sb + SM_A1H + aRowSel;
    const uint32_t bRowPart = (uint32_t)((lane & 7) + ((lane >> 4) & 1) * 8);
    const uint32_t bAddr64  = sb + SM_B + (nw * 64 + bRowPart) * ROWB + ((lane >> 3) & 1) * 16;
    const uint32_t bAddr32  = sb + SM_B + (nw * 32 + bRowPart) * ROWB + ((lane >> 3) & 1) * 16;

    float acc[2][8][4];
#pragma unroll
    for (int t = 0; t < 2; t++)
#pragma unroll
        for (int j = 0; j < 8; j++)
#pragma unroll
            for (int q = 0; q < 4; q++) acc[t][j][q] = 0.0f;

    // ---- front-loaded fills: A0, A1, B0 (single latency exposure) ----
#pragma unroll
    for (int op = 0; op < 2; op++) {
        const float* A = (op == 0) ? A0 : A1;
        const uint32_t base_h = (op == 0) ? SM_A0H : SM_A1H;
        const uint32_t base_l = (op == 0) ? SM_A0L : SM_A1L;
#pragma unroll
        for (int i = 0; i < 16; i++) {
            int g = tid + 256 * i;
            int r = g >> 5;
            int kb = (g & 31) << 2;
            int gr = m0 + r;
            float4 a = make_float4(0.f, 0.f, 0.f, 0.f);
            if (gr < M) a = *(const float4*)(A + (size_t)gr * FEAT + kb);
            __nv_bfloat16 hx = __float2bfloat16(a.x), hy = __float2bfloat16(a.y);
            __nv_bfloat16 hz = __float2bfloat16(a.z), hw = __float2bfloat16(a.w);
            uint2 hv, lv;
            {
                __nv_bfloat162 p0(hx, hy), p1(hz, hw);
                hv.x = *(uint32_t*)&p0; hv.y = *(uint32_t*)&p1;
            }
            lv.x = pack_bf16x2(a.x - __bfloat162float(hx), a.y - __bfloat162float(hy));
            lv.y = pack_bf16x2(a.z - __bfloat162float(hz), a.w - __bfloat162float(hw));
            uint32_t off = (uint32_t)r * ROWB + kb * 2;
            *(uint2*)(smem + base_h + off) = hv;
            *(uint2*)(smem + base_l + off) = lv;
        }
    }
#pragma unroll
    for (int i = 0; i < 8; i++) {
        int g = tid + 256 * i;
        int row = g >> 4, col = g & 15;
        uint32_t off = (uint32_t)row * ROWB + col * 16;
        *(uint4*)(smem + SM_B + off) = ((const uint4*)B0h)[g];
        *(uint4*)(smem + SM_B + B_LO_LAYER + off) = ((const uint4*)B0l)[g];
    }
    __syncthreads();

    // ---- op0 MMA ----
    mma_fused<4>(aAddr0, bAddr64, A_LO, B_LO_LAYER, acc);
    __syncthreads();

    // ---- swap in B1 (L2-hot blob) ----
#pragma unroll
    for (int i = 0; i < 8; i++) {
        int g = tid + 256 * i;
        int row = g >> 4, col = g & 15;
        uint32_t off = (uint32_t)row * ROWB + col * 16;
        *(uint4*)(smem + SM_B + off) = ((const uint4*)B1h)[g];
        *(uint4*)(smem + SM_B + B_LO_LAYER + off) = ((const uint4*)B1l)[g];
    }
    __syncthreads();

    // ---- op1 MMA ----
    mma_fused<4>(aAddr1, bAddr64, A_LO, B_LO_LAYER, acc);

    const int group = lane >> 2;
    const int tig   = lane & 3;

    if (!FC) {
#pragma unroll
        for (int t = 0; t < 2; t++) {
#pragma unroll
            for (int j = 0; j < 8; j++) {
                int col = nw * 64 + j * 8 + tig * 2;
                float2 b = *(const float2*)(bias + col);
                int r0 = m0 + mbase + t * 16 + group;
                float2 o0, o1;
                o0.x = fmaxf(acc[t][j][0] + b.x, 0.f); o0.y = fmaxf(acc[t][j][1] + b.y, 0.f);
                o1.x = fmaxf(acc[t][j][2] + b.x, 0.f); o1.y = fmaxf(acc[t][j][3] + b.y, 0.f);
                if (r0 < M)     *(float2*)(hout + (size_t)r0 * FEAT + col)       = o0;
                if (r0 + 8 < M) *(float2*)(hout + (size_t)(r0 + 8) * FEAT + col) = o1;
            }
        }
    } else {
        // ---- FC stage: h = relu(acc + b) -> A0 slot; Bfc -> B slot ----
        __syncthreads();
#pragma unroll
        for (int t = 0; t < 2; t++) {
#pragma unroll
            for (int j = 0; j < 8; j++) {
                int col = nw * 64 + j * 8 + tig * 2;
                float2 b = *(const float2*)(bias + col);
                int r0 = mbase + t * 16 + group;
                float h0v = fmaxf(acc[t][j][0] + b.x, 0.f);
                float h1v = fmaxf(acc[t][j][1] + b.y, 0.f);
                float h2v = fmaxf(acc[t][j][2] + b.x, 0.f);
                float h3v = fmaxf(acc[t][j][3] + b.y, 0.f);
                __nv_bfloat16 e0 = __float2bfloat16(h0v), e1 = __float2bfloat16(h1v);
                __nv_bfloat16 e2 = __float2bfloat16(h2v), e3 = __float2bfloat16(h3v);
                uint32_t hi0, hi1;
                {
                    __nv_bfloat162 p0(e0, e1), p1(e2, e3);
                    hi0 = *(uint32_t*)&p0; hi1 = *(uint32_t*)&p1;
                }
                uint32_t lo0 = pack_bf16x2(h0v - __bfloat162float(e0), h1v - __bfloat162float(e1));
                uint32_t lo1 = pack_bf16x2(h2v - __bfloat162float(e2), h3v - __bfloat162float(e3));
                uint32_t off0 = (uint32_t)r0 * ROWB + col * 2;
                uint32_t off1 = (uint32_t)(r0 + 8) * ROWB + col * 2;
                *(uint32_t*)(smem + SM_A0H + off0) = hi0;
                *(uint32_t*)(smem + SM_A0L + off0) = lo0;
                *(uint32_t*)(smem + SM_A0H + off1) = hi1;
                *(uint32_t*)(smem + SM_A0L + off1) = lo1;
            }
        }
#pragma unroll
        for (int i = 0; i < 4; i++) {
            int g = tid + 256 * i;
            int row = g >> 4, col = g & 15;
            uint32_t off = (uint32_t)row * ROWB + col * 16;
            *(uint4*)(smem + SM_B + off) = ((const uint4*)Bfh)[g];
            *(uint4*)(smem + SM_B + B_LO_FC + off) = ((const uint4*)Bfl)[g];
        }
        __syncthreads();

        float accf[2][4][4];
#pragma unroll
        for (int t = 0; t < 2; t++)
#pragma unroll
            for (int j = 0; j < 4; j++)
#pragma unroll
                for (int q = 0; q < 4; q++) accf[t][j][q] = 0.0f;

        mma_fused<2>(aAddr0, bAddr32, A_LO, B_LO_FC, accf);

#pragma unroll
        for (int t = 0; t < 2; t++) {
#pragma unroll
            for (int j = 0; j < 4; j++) {
                int col = nw * 32 + j * 8 + tig * 2;
                float2 b = *(const float2*)(bfc + col);
                int r0 = m0 + mbase + t * 16 + group;
                float2 o0, o1;
                o0.x = accf[t][j][0] + b.x; o0.y = accf[t][j][1] + b.y;
                o1.x = accf[t][j][2] + b.x; o1.y = accf[t][j][3] + b.y;
                if (r0 < M)     *(float2*)(fcout + (size_t)r0 * 64 + col)       = o0;
                if (r0 + 8 < M) *(float2*)(fcout + (size_t)(r0 + 8) * 64 + col) = o1;
            }
        }
    }
}

// ===========================================================================
extern "C" void kernel_launch(void* const* d_in, const int* in_sizes, int n_in,
                              void* d_out, int out_size) {
    const float* x   = (const float*)d_in[0];
    const void*  ei  = d_in[1];
    const float* Wl0 = (const float*)d_in[2];
    const float* Wr0 = (const float*)d_in[3];
    const float* b0  = (const float*)d_in[4];
    const float* Wl1 = (const float*)d_in[5];
    const float* Wr1 = (const float*)d_in[6];
    const float* b1  = (const float*)d_in[7];
    const float* Wfc = (const float*)d_in[8];
    const float* bfc = (const float*)d_in[9];
    float*       out = (float*)d_out;

    const int M = in_sizes[0] / FEAT;   // 50000
    const int E = in_sizes[1] / 2;      // 800000

    float *dinv, *agg, *h0;
    int *degi, *offs, *cursor, *csr, *status;
    unsigned char* wb;
    cudaGetSymbolAddress((void**)&dinv, g_dinv);
    cudaGetSymbolAddress((void**)&agg,  g_agg);
    cudaGetSymbolAddress((void**)&h0,   g_h0);
    cudaGetSymbolAddress((void**)&degi, g_degi);
    cudaGetSymbolAddress((void**)&offs, g_offs);
    cudaGetSymbolAddress((void**)&cursor, g_cursor);
    cudaGetSymbolAddress((void**)&csr,  g_csr);
    cudaGetSymbolAddress((void**)&status, g_status);
    cudaGetSymbolAddress((void**)&wb,   g_wb);
    auto blob = [&](int w, int hl) { return wb + ((size_t)w * 2 + hl) * 32768; };

    cudaFuncSetAttribute(sage_gemm<false>, cudaFuncAttributeMaxDynamicSharedMemorySize, SMEM_TOTAL);
    cudaFuncSetAttribute(sage_gemm<true>,  cudaFuncAttributeMaxDynamicSharedMemorySize, SMEM_TOTAL);

    // K1: degree histogram + weight prep (per-block dtype detect; degi enters 0)
    const int degBlocks = (E + 255) / 256;
    degree_prep<<<degBlocks + 320, 256>>>(ei, degi, E, M, degBlocks,
                                          Wl0, Wr0, Wl1, Wr1, Wfc, wb);

    // K2: fused decoupled-lookback scan -> offs/cursor/dinv
    const int nb = (M + SCAN_BLK - 1) / SCAN_BLK;
    scan_fused<<<nb, SCAN_BLK>>>(degi, offs, cursor, dinv, status, M);

    // K3: CSR fill
    csr_fill<<<(E + 255) / 256, 256>>>(ei, cursor, csr, E, M);

    const int gatherBlocks = (M * 32 + 255) / 256;
    const int gemmBlocks   = (M + 127) / 128;

    // layer 0: h0 = relu(agg(x)@Wl0 + x@Wr0 + b0)
    gather_kernel<<<gatherBlocks, 256>>>(x, csr, offs, dinv, agg, degi, status, M);
    sage_gemm<false><<<gemmBlocks, 256, SMEM_TOTAL>>>(
        agg, x, blob(0, 0), blob(0, 1), blob(1, 0), blob(1, 1), b0, h0,
        nullptr, nullptr, nullptr, nullptr, M);

    // layer 1 + fc: out = relu(agg(h0)@Wl1 + h0@Wr1 + b1) @ Wfc + bfc
    gather_kernel<<<gatherBlocks, 256>>>(h0, csr, offs, dinv, agg, degi, status, M);
    sage_gemm<true><<<gemmBlocks, 256, SMEM_TOTAL>>>(
        agg, h0, blob(2, 0), blob(2, 1), blob(3, 0), blob(3, 1), b1, nullptr,
        blob(4, 0), blob(4, 1), bfc, out, M);
}